// round 3
// baseline (speedup 1.0000x reference)
#include <cuda_runtime.h>

// reblurWithKernel: out[b,c,h,w] = sum_{i,j in 0..2} img[b,c,clamp(h+i-1),clamp(w+j-1)] * K[i*3+j,h,w]
// Shapes: img [1,3,1024,1024] f32, K [9,1024,1024] f32, out [1,3,1024,1024] f32.
// HBM-bound: 36MB kernels + 12MB img + 12MB out. Each thread: 4 pixels (float4) x 3 channels,
// so the dominant Kernels stream is read exactly once, fully coalesced.

#define H 1024
#define W 1024
#define HW (H * W)

__global__ __launch_bounds__(256)
void reblur_kernel(const float* __restrict__ img,
                   const float* __restrict__ ker,
                   float* __restrict__ out)
{
    const int idx = blockIdx.x * blockDim.x + threadIdx.x;   // one per 4-pixel group
    const int w4 = idx & (W / 4 - 1);                        // 0..255
    const int h  = idx >> 8;                                 // 0..1023
    const int w0 = w4 << 2;

    const int hm = (h > 0)     ? h - 1 : 0;
    const int hp = (h < H - 1) ? h + 1 : H - 1;

    // 9 per-pixel kernel taps, vectorized over the 4 pixels
    float4 k[9];
    const float* kp = ker + h * W + w0;
    #pragma unroll
    for (int t = 0; t < 9; t++)
        k[t] = *reinterpret_cast<const float4*>(kp + t * HW);

    const int rows[3] = {hm, h, hp};
    const int wl = (w0 > 0) ? w0 - 1 : 0;          // left halo (clamped)
    const int wr = (w0 + 4 < W) ? w0 + 4 : W - 1;  // right halo (clamped)

    #pragma unroll
    for (int c = 0; c < 3; c++) {
        const float* base = img + c * HW;
        float row[3][6];
        #pragma unroll
        for (int r = 0; r < 3; r++) {
            const float* p = base + rows[r] * W;
            float4 mid = *reinterpret_cast<const float4*>(p + w0);
            row[r][0] = p[wl];
            row[r][1] = mid.x; row[r][2] = mid.y;
            row[r][3] = mid.z; row[r][4] = mid.w;
            row[r][5] = p[wr];
        }

        float acc0 = 0.f, acc1 = 0.f, acc2 = 0.f, acc3 = 0.f;
        #pragma unroll
        for (int r = 0; r < 3; r++) {
            #pragma unroll
            for (int dx = 0; dx < 3; dx++) {
                const float4 kv = k[r * 3 + dx];
                acc0 = fmaf(row[r][0 + dx], kv.x, acc0);
                acc1 = fmaf(row[r][1 + dx], kv.y, acc1);
                acc2 = fmaf(row[r][2 + dx], kv.z, acc2);
                acc3 = fmaf(row[r][3 + dx], kv.w, acc3);
            }
        }

        float4 o; o.x = acc0; o.y = acc1; o.z = acc2; o.w = acc3;
        *reinterpret_cast<float4*>(out + c * HW + h * W + w0) = o;
    }
}

extern "C" void kernel_launch(void* const* d_in, const int* in_sizes, int n_in,
                              void* d_out, int out_size)
{
    const float* img = (const float*)d_in[0];   // [1,3,1024,1024]
    const float* ker = (const float*)d_in[1];   // [9,1024,1024]
    float* out = (float*)d_out;                 // [1,3,1024,1024]

    const int groups = H * (W / 4);             // 262144 threads
    reblur_kernel<<<groups / 256, 256>>>(img, ker, out);
}